// round 14
// baseline (speedup 1.0000x reference)
#include <cuda_runtime.h>

// MultiPartLoss: YOLO-style loss over (N, 49, 30) preds/targets, fp32.
// Persistent kernel, ONE block per SM, 3-stage TMA (cp.async.bulk) smem
// pipeline with 38.4 KB bulk requests + L2 evict-first streaming hint,
// contiguous per-block tile spans -> 2 long sequential DRAM streams/SM.
// Conflict-free float2 smem compute; fused last-block finalize (non-pow2
// safe tree; scratch reuses dynamic smem so 230.4 KB pipeline fits).

#define C_CLS 20
#define F 30
#define F2 (F / 2)
#define TPB 320                        // cells per tile (NOT pow2!)
#define STAGES 3
#define STAGE_FLOATS (TPB * F)         // 9600 floats per tensor per stage
#define STAGE_BYTES_T (STAGE_FLOATS * 4)     // 38400 B per tensor
#define STAGE_TOTAL (2 * STAGE_FLOATS)       // 19200 floats
#define STAGE_BYTES (STAGE_TOTAL * 4)        // 76800 B
#define SMEM_BYTES (STAGES * STAGE_BYTES)    // 230400 B dynamic smem
#define NBLK 148                       // one block per SM
#define MAX_PART 4096
#define NOOBJ 0.5f

__device__ float g_partials[MAX_PART];
__device__ unsigned int g_count = 0;

extern __shared__ float smem[];        // [stage][tensor][STAGE_FLOATS]

__device__ __forceinline__ unsigned int smem_u32(const void* p) {
    return (unsigned int)__cvta_generic_to_shared(p);
}

// Bulk copy with L2 evict-first policy: pure streaming data, no reuse.
__device__ __forceinline__ void bulk_copy_stream(void* smem_dst,
                                                 const void* gmem_src,
                                                 unsigned int bytes,
                                                 unsigned int mbar) {
    asm volatile(
        "{\n\t"
        ".reg .b64 policy;\n\t"
        "createpolicy.fractional.L2::evict_first.b64 policy, 1.0;\n\t"
        "cp.async.bulk.shared::cta.global.mbarrier::complete_tx::bytes"
        ".L2::cache_hint [%0], [%1], %2, [%3], policy;\n\t"
        "}"
        :: "r"(smem_u32(smem_dst)), "l"(gmem_src), "r"(bytes), "r"(mbar)
        : "memory");
}

__device__ __forceinline__ void mbar_wait(unsigned int mbar, unsigned int parity) {
    unsigned int done;
    asm volatile(
        "{\n\t.reg .pred p;\n\t"
        "mbarrier.try_wait.parity.acquire.cta.shared::cta.b64 p, [%1], %2;\n\t"
        "selp.b32 %0, 1, 0, p;\n\t}"
        : "=r"(done) : "r"(mbar), "r"(parity) : "memory");
    if (!done) {
        asm volatile(
            "{\n\t.reg .pred P1;\n\t"
            "WAIT_LOOP_%=:\n\t"
            "mbarrier.try_wait.parity.acquire.cta.shared::cta.b64 P1, [%0], %1, 0x989680;\n\t"
            "@P1 bra.uni WAIT_DONE_%=;\n\t"
            "bra.uni WAIT_LOOP_%=;\n\t"
            "WAIT_DONE_%=:\n\t}"
            :: "r"(mbar), "r"(parity) : "memory");
    }
}

__device__ __forceinline__ void produce(int s, int tile,
                                        const float* __restrict__ preds,
                                        const float* __restrict__ targets,
                                        unsigned int mbar) {
    if (threadIdx.x == 0) {
        float* sp = smem + s * STAGE_TOTAL;
        const long long base = (long long)tile * STAGE_FLOATS;
        asm volatile(
            "mbarrier.arrive.expect_tx.shared::cta.b64 _, [%0], %1;"
            :: "r"(mbar), "r"((unsigned int)STAGE_BYTES) : "memory");
        bulk_copy_stream(sp, preds + base, STAGE_BYTES_T, mbar);
        bulk_copy_stream(sp + STAGE_FLOATS, targets + base, STAGE_BYTES_T, mbar);
    }
}

__device__ __forceinline__ float compute_cell(int stage, int tile, int M)
{
    const int cell = tile * TPB + threadIdx.x;
    if (cell >= M) return 0.0f;

    // 30 floats per cell (120 B, 8B-aligned) -> 15 aligned float2 loads.
    const float2* p2 = (const float2*)(smem + stage * STAGE_TOTAL) + threadIdx.x * F2;
    const float2* t2 = p2 + (STAGE_FLOATS / 2);

    float2 pc = p2[10];
    float2 tc = t2[10];
    float dc0 = pc.x - tc.x;
    float dc1 = pc.y - tc.y;
    float l = NOOBJ * (dc0 * dc0 + dc1 * dc1);

    // obj: class targets are one-hot * obj -> sum is exactly 0 or 1
    float s = 0.0f;
    float2 tcl[10];
    #pragma unroll
    for (int c = 0; c < 10; c++) {
        tcl[c] = t2[c];
        s += tcl[c].x + tcl[c].y;
    }
    const bool obj = (s == 1.0f);

    if (obj) {
        float2 pxy0 = p2[11], pwh0 = p2[12], pxy1 = p2[13], pwh1 = p2[14];
        float2 txy0 = t2[11], twh0 = t2[12], txy1 = t2[13], twh1 = t2[14];

        float iou[2];
        #pragma unroll
        for (int b = 0; b < 2; b++) {
            float px = b ? pxy1.x : pxy0.x, py = b ? pxy1.y : pxy0.y;
            float pw = b ? pwh1.x : pwh0.x, ph = b ? pwh1.y : pwh0.y;
            float tx = b ? txy1.x : txy0.x, ty = b ? txy1.y : txy0.y;
            float tw = b ? twh1.x : twh0.x, th = b ? twh1.y : twh0.y;
            float xA = fmaxf(px - pw * 0.5f, tx - tw * 0.5f);
            float xB = fminf(px + pw * 0.5f, tx + tw * 0.5f);
            float yA = fmaxf(py - ph * 0.5f, ty - th * 0.5f);
            float yB = fminf(py + ph * 0.5f, ty + th * 0.5f);
            float inter = fmaxf(0.0f, xB - xA + 1.0f) *
                          fmaxf(0.0f, yB - yA + 1.0f);
            float uni = pw * ph + tw * th - inter;
            iou[b] = inter / uni;
        }
        const bool top1 = (iou[1] > iou[0]);   // argmax: first max wins

        float dct = (top1 ? pc.y : pc.x) - (top1 ? tc.y : tc.x);
        l += (1.0f - NOOBJ) * dct * dct;

        float cls = 0.0f;
        #pragma unroll
        for (int c = 0; c < 10; c++) {
            float2 pcl = p2[c];
            float dx = pcl.x - tcl[c].x;
            float dy = pcl.y - tcl[c].y;
            cls += dx * dx + dy * dy;
        }
        l += cls;

        float2 pxy = top1 ? pxy1 : pxy0;
        float2 txy = top1 ? txy1 : txy0;
        float dx = pxy.x - txy.x;
        float dy = pxy.y - txy.y;
        l += dx * dx + dy * dy;

        float2 pwh = top1 ? pwh1 : pwh0;
        float2 twh = top1 ? twh1 : twh0;
        float dw = sqrtf(pwh.x) - sqrtf(twh.x);
        float dh = sqrtf(pwh.y) - sqrtf(twh.y);
        l += dw * dw + dh * dh;
    }
    return l;
}

__global__ __launch_bounds__(TPB, 1) void mploss_320f(
    const float* __restrict__ preds,
    const float* __restrict__ targets,
    int M, float invN, float* __restrict__ out)
{
    __shared__ __align__(8) unsigned long long mbar_storage[STAGES];
    __shared__ bool s_is_last;
    __shared__ float warp_sums[TPB / 32];

    const long long totalFloats = (long long)M * F;
    const int numTiles = (M + TPB - 1) / TPB;

    // Contiguous per-block span: first `rem` blocks take one extra tile.
    const int per  = numTiles / gridDim.x;
    const int rem  = numTiles % gridDim.x;
    const int bid  = blockIdx.x;
    const int tileBeg = bid * per + (bid < rem ? bid : rem);
    const int tileEnd = tileBeg + per + (bid < rem ? 1 : 0);

    if (threadIdx.x == 0) {
        #pragma unroll
        for (int s = 0; s < STAGES; s++) {
            unsigned int a = smem_u32(&mbar_storage[s]);
            asm volatile("mbarrier.init.shared::cta.b64 [%0], 1;" :: "r"(a) : "memory");
        }
        asm volatile("fence.proxy.async.shared::cta;" ::: "memory");
    }
    __syncthreads();

    unsigned int mbar[STAGES];
    #pragma unroll
    for (int s = 0; s < STAGES; s++) mbar[s] = smem_u32(&mbar_storage[s]);

    // Prologue: prefetch up to STAGES consecutive tiles.
    #pragma unroll
    for (int k = 0; k < STAGES; k++) {
        int tk = tileBeg + k;
        if (tk < tileEnd &&
            (long long)(tk + 1) * STAGE_FLOATS <= totalFloats)
            produce(k, tk, preds, targets, mbar[k]);
    }

    float acc = 0.0f;
    unsigned int phases = 0;
    int s = 0;

    for (int tile = tileBeg; tile < tileEnd; tile++) {
        const bool full = ((long long)(tile + 1) * STAGE_FLOATS <= totalFloats);

        if (full) {
            mbar_wait(mbar[s], (phases >> s) & 1u);
            phases ^= (1u << s);
        } else {
            // tail tile (hit once): cooperative direct loads
            float* sp = smem + s * STAGE_TOTAL;
            float* st = sp + STAGE_FLOATS;
            const long long base = (long long)tile * STAGE_FLOATS;
            const int remaining = (int)(totalFloats - base);
            for (int i = threadIdx.x; i < remaining; i += TPB) {
                sp[i] = preds[base + i];
                st[i] = targets[base + i];
            }
            __syncthreads();
        }

        acc += compute_cell(s, tile, M);
        __syncthreads();   // all threads done reading stage s

        const int next = tile + STAGES;
        if (next < tileEnd &&
            (long long)(next + 1) * STAGE_FLOATS <= totalFloats)
            produce(s, next, preds, targets, mbar[s]);

        s = (s + 1 == STAGES) ? 0 : s + 1;
    }

    // Deterministic per-block reduction (warp shuffle, fixed order).
    #pragma unroll
    for (int off = 16; off > 0; off >>= 1)
        acc += __shfl_down_sync(0xFFFFFFFFu, acc, off);

    const int lane = threadIdx.x & 31;
    const int wid  = threadIdx.x >> 5;
    if (lane == 0) warp_sums[wid] = acc;
    __syncthreads();

    if (threadIdx.x == 0) {
        float bsum = 0.0f;
        #pragma unroll
        for (int w = 0; w < TPB / 32; w++) bsum += warp_sums[w];
        g_partials[blockIdx.x] = bsum;
        __threadfence();
        unsigned int prev = atomicAdd(&g_count, 1u);
        s_is_last = (prev == gridDim.x - 1);
    }
    __syncthreads();

    // Last finished block: deterministic double-precision finalize.
    // Scratch reuses dynamic smem (pipeline stages are dead here).
    // NON-POW2 SAFE: pre-fold all 320 slots into 64, then pow2 tree.
    if (s_is_last) {
        double* dsum = (double*)smem;
        double d = 0.0;
        for (int i = threadIdx.x; i < (int)gridDim.x; i += TPB)
            d += (double)g_partials[i];
        dsum[threadIdx.x] = d;
        __syncthreads();

        if (threadIdx.x < 64) {
            double v = dsum[threadIdx.x];
            #pragma unroll
            for (int k = 1; k < TPB / 64; k++)      // 64,128,192,256 offsets
                v += dsum[threadIdx.x + k * 64];
            dsum[threadIdx.x] = v;
        }
        __syncthreads();

        #pragma unroll
        for (int stride = 32; stride > 0; stride >>= 1) {
            if (threadIdx.x < stride)
                dsum[threadIdx.x] += dsum[threadIdx.x + stride];
            __syncthreads();
        }
        if (threadIdx.x == 0) {
            out[0] = (float)(dsum[0] * (double)invN);
            g_count = 0;   // reset for next graph replay
        }
    }
}

extern "C" void kernel_launch(void* const* d_in, const int* in_sizes, int n_in,
                              void* d_out, int out_size)
{
    const float* preds   = (const float*)d_in[0];
    const float* targets = (const float*)d_in[1];
    float* out = (float*)d_out;

    const int M = in_sizes[0] / F;
    const int N = M / 49;
    const float invN = 1.0f / (float)N;

    cudaFuncSetAttribute(mploss_320f,
                         cudaFuncAttributeMaxDynamicSharedMemorySize,
                         SMEM_BYTES);

    const int numTiles = (M + TPB - 1) / TPB;
    int nblk = NBLK;
    if (nblk > numTiles) nblk = numTiles;
    if (nblk > MAX_PART) nblk = MAX_PART;

    mploss_320f<<<nblk, TPB, SMEM_BYTES>>>(preds, targets, M, invN, out);
}

// round 15
// speedup vs baseline: 1.0447x; 1.0447x over previous
#include <cuda_runtime.h>

// MultiPartLoss: YOLO-style loss over (N, 49, 30) preds/targets, fp32.
// Persistent kernel, <=1 block per SM, 3-stage TMA (cp.async.bulk) smem
// pipeline with 30 KB bulk requests + L2 evict-first streaming hint,
// contiguous per-block tile spans. Grid picked so tiles divide EXACTLY
// (128 blocks x 49 tiles for the bench shape -> zero tail imbalance).
// Conflict-free float2 smem compute; fused last-block finalize.

#define C_CLS 20
#define F 30
#define F2 (F / 2)
#define TPB 256                        // cells per tile
#define STAGES 3
#define STAGE_FLOATS (TPB * F)         // 7680 floats per tensor per stage
#define STAGE_BYTES_T (STAGE_FLOATS * 4)     // 30720 B per tensor
#define STAGE_TOTAL (2 * STAGE_FLOATS)       // 15360 floats
#define STAGE_BYTES (STAGE_TOTAL * 4)        // 61440 B
#define SMEM_BYTES (STAGES * STAGE_BYTES)    // 184320 B dynamic smem
#define NBLK_MAX 148                   // at most one block per SM
#define MAX_PART 4096
#define NOOBJ 0.5f

__device__ float g_partials[MAX_PART];
__device__ unsigned int g_count = 0;

extern __shared__ float smem[];        // [stage][tensor][STAGE_FLOATS]

__device__ __forceinline__ unsigned int smem_u32(const void* p) {
    return (unsigned int)__cvta_generic_to_shared(p);
}

// Bulk copy with L2 evict-first policy: pure streaming data, no reuse.
__device__ __forceinline__ void bulk_copy_stream(void* smem_dst,
                                                 const void* gmem_src,
                                                 unsigned int bytes,
                                                 unsigned int mbar) {
    asm volatile(
        "{\n\t"
        ".reg .b64 policy;\n\t"
        "createpolicy.fractional.L2::evict_first.b64 policy, 1.0;\n\t"
        "cp.async.bulk.shared::cta.global.mbarrier::complete_tx::bytes"
        ".L2::cache_hint [%0], [%1], %2, [%3], policy;\n\t"
        "}"
        :: "r"(smem_u32(smem_dst)), "l"(gmem_src), "r"(bytes), "r"(mbar)
        : "memory");
}

__device__ __forceinline__ void mbar_wait(unsigned int mbar, unsigned int parity) {
    unsigned int done;
    asm volatile(
        "{\n\t.reg .pred p;\n\t"
        "mbarrier.try_wait.parity.acquire.cta.shared::cta.b64 p, [%1], %2;\n\t"
        "selp.b32 %0, 1, 0, p;\n\t}"
        : "=r"(done) : "r"(mbar), "r"(parity) : "memory");
    if (!done) {
        asm volatile(
            "{\n\t.reg .pred P1;\n\t"
            "WAIT_LOOP_%=:\n\t"
            "mbarrier.try_wait.parity.acquire.cta.shared::cta.b64 P1, [%0], %1, 0x989680;\n\t"
            "@P1 bra.uni WAIT_DONE_%=;\n\t"
            "bra.uni WAIT_LOOP_%=;\n\t"
            "WAIT_DONE_%=:\n\t}"
            :: "r"(mbar), "r"(parity) : "memory");
    }
}

__device__ __forceinline__ void produce(int s, int tile,
                                        const float* __restrict__ preds,
                                        const float* __restrict__ targets,
                                        unsigned int mbar) {
    if (threadIdx.x == 0) {
        float* sp = smem + s * STAGE_TOTAL;
        const long long base = (long long)tile * STAGE_FLOATS;
        asm volatile(
            "mbarrier.arrive.expect_tx.shared::cta.b64 _, [%0], %1;"
            :: "r"(mbar), "r"((unsigned int)STAGE_BYTES) : "memory");
        bulk_copy_stream(sp, preds + base, STAGE_BYTES_T, mbar);
        bulk_copy_stream(sp + STAGE_FLOATS, targets + base, STAGE_BYTES_T, mbar);
    }
}

__device__ __forceinline__ float compute_cell(int stage, int tile, int M)
{
    const int cell = tile * TPB + threadIdx.x;
    if (cell >= M) return 0.0f;

    // 30 floats per cell (120 B, 8B-aligned) -> 15 aligned float2 loads.
    const float2* p2 = (const float2*)(smem + stage * STAGE_TOTAL) + threadIdx.x * F2;
    const float2* t2 = p2 + (STAGE_FLOATS / 2);

    float2 pc = p2[10];
    float2 tc = t2[10];
    float dc0 = pc.x - tc.x;
    float dc1 = pc.y - tc.y;
    float l = NOOBJ * (dc0 * dc0 + dc1 * dc1);

    // obj: class targets are one-hot * obj -> sum is exactly 0 or 1
    float s = 0.0f;
    float2 tcl[10];
    #pragma unroll
    for (int c = 0; c < 10; c++) {
        tcl[c] = t2[c];
        s += tcl[c].x + tcl[c].y;
    }
    const bool obj = (s == 1.0f);

    if (obj) {
        float2 pxy0 = p2[11], pwh0 = p2[12], pxy1 = p2[13], pwh1 = p2[14];
        float2 txy0 = t2[11], twh0 = t2[12], txy1 = t2[13], twh1 = t2[14];

        float iou[2];
        #pragma unroll
        for (int b = 0; b < 2; b++) {
            float px = b ? pxy1.x : pxy0.x, py = b ? pxy1.y : pxy0.y;
            float pw = b ? pwh1.x : pwh0.x, ph = b ? pwh1.y : pwh0.y;
            float tx = b ? txy1.x : txy0.x, ty = b ? txy1.y : txy0.y;
            float tw = b ? twh1.x : twh0.x, th = b ? twh1.y : twh0.y;
            float xA = fmaxf(px - pw * 0.5f, tx - tw * 0.5f);
            float xB = fminf(px + pw * 0.5f, tx + tw * 0.5f);
            float yA = fmaxf(py - ph * 0.5f, ty - th * 0.5f);
            float yB = fminf(py + ph * 0.5f, ty + th * 0.5f);
            float inter = fmaxf(0.0f, xB - xA + 1.0f) *
                          fmaxf(0.0f, yB - yA + 1.0f);
            float uni = pw * ph + tw * th - inter;
            iou[b] = inter / uni;
        }
        const bool top1 = (iou[1] > iou[0]);   // argmax: first max wins

        float dct = (top1 ? pc.y : pc.x) - (top1 ? tc.y : tc.x);
        l += (1.0f - NOOBJ) * dct * dct;

        float cls = 0.0f;
        #pragma unroll
        for (int c = 0; c < 10; c++) {
            float2 pcl = p2[c];
            float dx = pcl.x - tcl[c].x;
            float dy = pcl.y - tcl[c].y;
            cls += dx * dx + dy * dy;
        }
        l += cls;

        float2 pxy = top1 ? pxy1 : pxy0;
        float2 txy = top1 ? txy1 : txy0;
        float dx = pxy.x - txy.x;
        float dy = pxy.y - txy.y;
        l += dx * dx + dy * dy;

        float2 pwh = top1 ? pwh1 : pwh0;
        float2 twh = top1 ? twh1 : twh0;
        float dw = sqrtf(pwh.x) - sqrtf(twh.x);
        float dh = sqrtf(pwh.y) - sqrtf(twh.y);
        l += dw * dw + dh * dh;
    }
    return l;
}

__global__ __launch_bounds__(TPB, 1) void mploss_bal(
    const float* __restrict__ preds,
    const float* __restrict__ targets,
    int M, float invN, float* __restrict__ out)
{
    __shared__ __align__(8) unsigned long long mbar_storage[STAGES];
    __shared__ bool s_is_last;
    __shared__ float warp_sums[TPB / 32];
    __shared__ double dsum[TPB];

    const long long totalFloats = (long long)M * F;
    const int numTiles = (M + TPB - 1) / TPB;

    // Contiguous per-block span: first `rem` blocks take one extra tile.
    const int per  = numTiles / gridDim.x;
    const int rem  = numTiles % gridDim.x;
    const int bid  = blockIdx.x;
    const int tileBeg = bid * per + (bid < rem ? bid : rem);
    const int tileEnd = tileBeg + per + (bid < rem ? 1 : 0);

    if (threadIdx.x == 0) {
        #pragma unroll
        for (int s = 0; s < STAGES; s++) {
            unsigned int a = smem_u32(&mbar_storage[s]);
            asm volatile("mbarrier.init.shared::cta.b64 [%0], 1;" :: "r"(a) : "memory");
        }
        asm volatile("fence.proxy.async.shared::cta;" ::: "memory");
    }
    __syncthreads();

    unsigned int mbar[STAGES];
    #pragma unroll
    for (int s = 0; s < STAGES; s++) mbar[s] = smem_u32(&mbar_storage[s]);

    // Prologue: prefetch up to STAGES consecutive tiles.
    #pragma unroll
    for (int k = 0; k < STAGES; k++) {
        int tk = tileBeg + k;
        if (tk < tileEnd &&
            (long long)(tk + 1) * STAGE_FLOATS <= totalFloats)
            produce(k, tk, preds, targets, mbar[k]);
    }

    float acc = 0.0f;
    unsigned int phases = 0;
    int s = 0;

    for (int tile = tileBeg; tile < tileEnd; tile++) {
        const bool full = ((long long)(tile + 1) * STAGE_FLOATS <= totalFloats);

        if (full) {
            mbar_wait(mbar[s], (phases >> s) & 1u);
            phases ^= (1u << s);
        } else {
            // tail tile (not hit for the bench shape): cooperative loads
            float* sp = smem + s * STAGE_TOTAL;
            float* st = sp + STAGE_FLOATS;
            const long long base = (long long)tile * STAGE_FLOATS;
            const int remaining = (int)(totalFloats - base);
            for (int i = threadIdx.x; i < remaining; i += TPB) {
                sp[i] = preds[base + i];
                st[i] = targets[base + i];
            }
            __syncthreads();
        }

        acc += compute_cell(s, tile, M);
        __syncthreads();   // all threads done reading stage s

        const int next = tile + STAGES;
        if (next < tileEnd &&
            (long long)(next + 1) * STAGE_FLOATS <= totalFloats)
            produce(s, next, preds, targets, mbar[s]);

        s = (s + 1 == STAGES) ? 0 : s + 1;
    }

    // Deterministic per-block reduction.
    #pragma unroll
    for (int off = 16; off > 0; off >>= 1)
        acc += __shfl_down_sync(0xFFFFFFFFu, acc, off);

    const int lane = threadIdx.x & 31;
    const int wid  = threadIdx.x >> 5;
    if (lane == 0) warp_sums[wid] = acc;
    __syncthreads();

    if (threadIdx.x == 0) {
        float bsum = 0.0f;
        #pragma unroll
        for (int w = 0; w < TPB / 32; w++) bsum += warp_sums[w];
        g_partials[blockIdx.x] = bsum;
        __threadfence();
        unsigned int prev = atomicAdd(&g_count, 1u);
        s_is_last = (prev == gridDim.x - 1);
    }
    __syncthreads();

    // Last finished block: deterministic double-precision finalize.
    if (s_is_last) {
        double d = 0.0;
        for (int i = threadIdx.x; i < (int)gridDim.x; i += TPB)
            d += (double)g_partials[i];
        dsum[threadIdx.x] = d;
        __syncthreads();
        #pragma unroll
        for (int stride = TPB / 2; stride > 0; stride >>= 1) {
            if (threadIdx.x < stride) dsum[threadIdx.x] += dsum[threadIdx.x + stride];
            __syncthreads();
        }
        if (threadIdx.x == 0) {
            out[0] = (float)(dsum[0] * (double)invN);
            g_count = 0;   // reset for next graph replay
        }
    }
}

extern "C" void kernel_launch(void* const* d_in, const int* in_sizes, int n_in,
                              void* d_out, int out_size)
{
    const float* preds   = (const float*)d_in[0];
    const float* targets = (const float*)d_in[1];
    float* out = (float*)d_out;

    const int M = in_sizes[0] / F;
    const int N = M / 49;
    const float invN = 1.0f / (float)N;

    cudaFuncSetAttribute(mploss_bal,
                         cudaFuncAttributeMaxDynamicSharedMemorySize,
                         SMEM_BYTES);

    const int numTiles = (M + TPB - 1) / TPB;

    // Largest grid <= NBLK_MAX that divides numTiles exactly; else NBLK_MAX.
    int nblk = NBLK_MAX;
    for (int g = NBLK_MAX; g >= NBLK_MAX / 2; g--) {
        if (numTiles % g == 0) { nblk = g; break; }
    }
    if (nblk > numTiles) nblk = numTiles;
    if (nblk > MAX_PART) nblk = MAX_PART;

    mploss_bal<<<nblk, TPB, SMEM_BYTES>>>(preds, targets, M, invN, out);
}